// round 13
// baseline (speedup 1.0000x reference)
#include <cuda_runtime.h>
#include <math.h>

#define NB 8192
#define SPIN 365
#define TRAIN 6000
#define NSTD (TRAIN - SPIN)   // 5635
#define L2E 1.4426950408889634f

#define CHUNK 16
#define NCHUNK (NB / CHUNK)   // 512
#define NCHUNKP (NCHUNK + 1)  // 513: pad for conflict-free SMEM transpose
#define NPASS 2
#define EXPB 32               // expand blocks; grid = 1 + EXPB

// natural-layout carry (coalesced on both sides)
__device__ float g_carry[NB];
__device__ int   g_flag;   // 0 -> 1 by scan block; reset by last expand block
__device__ int   g_done;

__device__ __forceinline__ float ex2f(float x) {
    float r;
    asm("ex2.approx.f32 %0, %1;" : "=f"(r) : "f"(x));
    return r;
}
__device__ __forceinline__ float tanh_approx(float x) {
    float r;
    asm("tanh.approx.f32 %0, %1;" : "=f"(r) : "f"(x));
    return r;
}
__device__ __forceinline__ float fsig(float x) {
    return __fdividef(1.0f, 1.0f + __expf(-x));
}

// ---------------------------------------------------------------------------
// One kernel, 33 blocks x 1024 threads, all co-resident:
//   block 0      : stage x -> 2-pass chunked scan -> g_carry -> flag=1
//   blocks 1-32  : (pre-flag) constants + obs_std + zero cols + u2 prefetch,
//                  (post-flag) read g_carry, compute + store 13 columns,
//                  last block resets flag for graph replay
// ---------------------------------------------------------------------------
__global__ void __launch_bounds__(1024, 1) mcp_one(
    const float* __restrict__ x,
    const float* __restrict__ y_obs,
    const float* __restrict__ p_mean_p,
    const float* __restrict__ p_std_p,
    const int*   __restrict__ time_lag_p,
    const float* __restrict__ w_r_yom_p,
    const float* __restrict__ w_r_ylm_p,
    const float* __restrict__ w_r_yfm_p,
    const float* __restrict__ w_r_yvm_p,
    const float* __restrict__ b0_yom_p,
    const float* __restrict__ b1_yom_p,
    const float* __restrict__ b2_yom_p,
    const float* __restrict__ b0_ylm_p,
    const float* __restrict__ b1_ylm_p,
    const float* __restrict__ b2_ylm_p,
    const float* __restrict__ w_s_yvm_p,
    const float* __restrict__ b0_yrm_p,
    float* __restrict__ out)
{
    extern __shared__ float sm[];          // scan block only
    __shared__ float redS[32];
    __shared__ float redQ[32];
    __shared__ float s_std_sh;
    __shared__ float s_seed[NCHUNK + 1];

    const int tid = threadIdx.x;
    const int wid = tid >> 5;
    const int lid = tid & 31;

    const float mo = *p_mean_p;
    const float so = *p_std_p;
    int time_lag = *time_lag_p;
    if (time_lag < 0)  time_lag = 0;
    if (time_lag > NB) time_lag = NB;

    const float inv_so = __fdividef(1.0f, so);
    const float Bl = (*b1_ylm_p) * inv_so;
    const float Kl = (*b0_ylm_p) - mo * Bl;
    const float b2l_over_SL = (*b2_ylm_p) * (1.0f / 1.898f);

    if (blockIdx.x == 0) {
        // =========================== SCAN BLOCK ===========================
        float* s_u1 = sm;
        float* s_u2 = sm + CHUNK * NCHUNKP;
        float* s_ag = sm + 2 * CHUNK * NCHUNKP;
        float* s_c  = sm + 3 * CHUNK * NCHUNKP;

        // stage x (coalesced LDG.64, padded STS)
        const float2* x2 = (const float2*)x;
        for (int i = tid; i < NB; i += 1024) {
            int k = i >> 4;
            int j = i & (CHUNK - 1);
            float2 v = x2[i];
            int a = j * NCHUNKP + k;
            s_u1[a] = v.x;
            s_u2[a] = v.y;
            s_ag[a] = -L2E * (Kl + (v.y - 2.9086f) * b2l_over_SL);
        }
        __syncthreads();

        if (wid < 16) {
            const float eo    = __expf(*w_r_yom_p);
            const float el    = __expf(*w_r_ylm_p);
            const float ef    = __expf(*w_r_yfm_p);
            const float denom = eo + el + ef;
            const float co    = __fdividef(eo, denom);
            const float cl    = __fdividef(el, denom);

            const float Bo  = (*b1_yom_p) * inv_so;
            const float Ko  = (*b0_yom_p) - mo * Bo - mo * inv_so * (*b2_yom_p);
            const float Bo2 = -L2E * Bo;
            const float Ko2 = -L2E * Ko;
            const float Bl2 = -L2E * Bl;

            const float sv  = fsig(*w_r_yvm_p);
            const float es  = __expf(*w_s_yvm_p);
            const float ebr = __expf(*b0_yrm_p);
            const float thresh = ebr * 500.0f;
            const float Ct = es * (1.0f / 500.0f);
            const float Dt = ebr * es;

            const int k     = tid;          // chunk id, 0..511
            const int begin = k * CHUNK;

            #pragma unroll
            for (int pass = 0; pass < NPASS; ++pass) {
                const bool last = (pass == NPASS - 1);
                float c = (pass == 0 || k == 0) ? 0.0f : s_seed[k];

                #pragma unroll
                for (int j = 0; j < CHUNK; ++j) {
                    const int i = begin + j;
                    float u2 = s_u2[j * NCHUNKP + k];
                    float ag = s_ag[j * NCHUNKP + k];

                    float exo = ex2f(fmaf(c, Bo2, Ko2));
                    float exl = ex2f(fmaf(c, Bl2, ag));
                    float rc  = __fdividef(u2, c);
                    float th  = tanh_approx(fmaf(c, Ct, -Dt));

                    float oo  = co * __fdividef(1.0f, 1.0f + exo);
                    float ol  = cl * __fdividef(1.0f, 1.0f + exl);
                    float olc = (c > 0.0f) ? fminf(ol, rc) : ol;
                    float f   = 1.0f - (oo + olc);
                    float ov  = fminf(sv * th, f);
                    float mr  = ov * fabsf(c - thresh);
                    float c1  = fmaf(f, c, s_u1[j * NCHUNKP + k]) - mr;

                    if (last) s_c[j * NCHUNKP + k] = c;
                    if (i >= time_lag) c = c1;
                }
                if (!last) {
                    s_seed[k + 1] = c;
                    asm volatile("bar.sync 2, 512;" ::: "memory");
                }
            }
        }
        __syncthreads();

        // coalesced natural-layout carry writeback
        for (int i = tid; i < NB; i += 1024) {
            g_carry[i] = s_c[(i & (CHUNK - 1)) * NCHUNKP + (i >> 4)];
        }
        __threadfence();
        __syncthreads();
        if (tid == 0) atomicExch(&g_flag, 1);   // release
        return;
    }

    // ============================ EXPAND BLOCKS ============================
    // ---- pre-flag work (overlapped with the scan) ----

    // derived constants from params (no g_const dependency)
    const float eo    = __expf(*w_r_yom_p);
    const float el    = __expf(*w_r_ylm_p);
    const float ef    = __expf(*w_r_yfm_p);
    const float denom = eo + el + ef;
    const float co    = __fdividef(eo, denom);
    const float cl    = __fdividef(el, denom);

    const float Bo = (*b1_yom_p) * inv_so;
    const float Ko = (*b0_yom_p) - mo * Bo - mo * inv_so * (*b2_yom_p);

    const float sv  = fsig(*w_r_yvm_p);
    const float es  = __expf(*w_s_yvm_p);
    const float ebr = __expf(*b0_yrm_p);
    const float thresh = ebr * 500.0f;
    const float Ct2 = es * (2.0f / 500.0f);
    const float Dt2 = 2.0f * ebr * es;
    const float sv2 = 2.0f * sv;

    // obs_std (redundant per block; deterministic identical result)
    {
        float s = 0.0f, q = 0.0f;
        for (int i = SPIN + tid; i < TRAIN; i += 1024) {
            float v = y_obs[i];
            s += v;
            q = fmaf(v, v, q);
        }
        #pragma unroll
        for (int off = 16; off > 0; off >>= 1) {
            s += __shfl_down_sync(0xFFFFFFFFu, s, off);
            q += __shfl_down_sync(0xFFFFFFFFu, q, off);
        }
        if (lid == 0) { redS[wid] = s; redQ[wid] = q; }
        __syncthreads();
        if (tid == 0) {
            float S = 0.0f, Q = 0.0f;
            #pragma unroll
            for (int w = 0; w < 32; ++w) { S += redS[w]; Q += redQ[w]; }
            const float n = (float)NSTD;
            float var = (Q - __fdividef(S * S, n)) * __fdividef(1.0f, n - 1.0f);
            s_std_sh = sqrtf(var);
        }
        __syncthreads();
    }
    const float obsstd = s_std_sh;

    const int i = (blockIdx.x - 1) * 256 + tid;   // threads 256..1023 idle past here
    const bool active = (tid < 256);

    float u2 = 0.0f;
    if (active) {
        u2 = x[2 * i + 1];                 // prefetch
        out[4 * NB + i] = 0.0f;            // bp_n   (always 0)
        out[5 * NB + i] = 0.0f;            // Gate_ib(always 0)
    }

    // ---- wait for carry ----
    {
        volatile int* fp = &g_flag;
        while (*fp == 0) { __nanosleep(64); }
    }
    __threadfence();   // acquire: order g_carry loads after flag observation

    if (active) {
        if (i < time_lag) {
            out[0 * NB + i] = 0.0f;
            out[1 * NB + i] = 0.0f;
            out[2 * NB + i] = 0.0f;
            out[3 * NB + i] = 0.0f;
            out[6 * NB + i] = 0.0f;
            out[7 * NB + i] = 0.0f;
            out[8 * NB + i] = 0.0f;
            out[9 * NB + i] = 0.0f;
            out[10 * NB + 2 * i]     = 0.0f;
            out[10 * NB + 2 * i + 1] = 0.0f;
            out[12 * NB + i] = 0.0f;
            out[13 * NB + i] = 0.0f;
            out[14 * NB + i] = 0.0f;
        } else {
            const float c = g_carry[i];
            const float argl = Kl + (u2 - 2.9086f) * b2l_over_SL;

            float oo  = co * fsig(fmaf(c, Bo, Ko));
            float ol  = cl * fsig(fmaf(c, Bl, argl));
            float rc  = __fdividef(u2, c);
            float olc = (c > 0.0f) ? fminf(ol, rc) : ol;
            float f   = (1.0f - oo) - olc;
            float e2t = __expf(fmaf(c, Ct2, -Dt2));
            float ov1 = sv - __fdividef(sv2, e2t + 1.0f);   // sv * tanh (accurate)
            float ov  = fminf(ov1, f);
            float mr  = ov * fabsf(c - thresh);
            float h   = oo * c;

            out[0 * NB + i] = h;
            out[1 * NB + i] = c;
            out[2 * NB + i] = ol * c;
            out[3 * NB + i] = olc * c;
            out[6 * NB + i] = oo;
            out[7 * NB + i] = ol;
            out[8 * NB + i] = olc;
            out[9 * NB + i] = f;
            out[10 * NB + 2 * i]     = h;
            out[10 * NB + 2 * i + 1] = obsstd;
            out[12 * NB + i] = obsstd;
            out[13 * NB + i] = ov;
            out[14 * NB + i] = mr;
        }
    }

    // ---- reset protocol for graph replay ----
    __threadfence();
    __syncthreads();
    if (tid == 0) {
        int old = atomicAdd(&g_done, 1);
        if (old == EXPB - 1) {        // last expand block: everyone is past the spin
            g_done = 0;
            atomicExch(&g_flag, 0);
        }
    }
}

extern "C" void kernel_launch(void* const* d_in, const int* in_sizes, int n_in,
                              void* d_out, int out_size)
{
    const float* x        = (const float*)d_in[0];
    const float* y_obs    = (const float*)d_in[1];
    const float* p_mean   = (const float*)d_in[2];
    const float* p_std    = (const float*)d_in[3];
    const int*   time_lag = (const int*)  d_in[5];
    const float* w_r_yom  = (const float*)d_in[6];
    const float* w_r_ylm  = (const float*)d_in[7];
    const float* w_r_yfm  = (const float*)d_in[8];
    const float* w_r_yvm  = (const float*)d_in[9];
    const float* b0_yom   = (const float*)d_in[10];
    const float* b1_yom   = (const float*)d_in[11];
    const float* b2_yom   = (const float*)d_in[12];
    const float* b0_ylm   = (const float*)d_in[13];
    const float* b1_ylm   = (const float*)d_in[14];
    const float* b2_ylm   = (const float*)d_in[15];
    const float* w_s_yvm  = (const float*)d_in[16];
    const float* b0_yrm   = (const float*)d_in[17];

    float* out = (float*)d_out;

    size_t smem = 4 * CHUNK * NCHUNKP * sizeof(float);   // ~128.3 KB dynamic
    cudaFuncSetAttribute(mcp_one,
                         cudaFuncAttributeMaxDynamicSharedMemorySize, (int)smem);

    mcp_one<<<1 + EXPB, 1024, smem>>>(
        x, y_obs, p_mean, p_std, time_lag,
        w_r_yom, w_r_ylm, w_r_yfm, w_r_yvm,
        b0_yom, b1_yom, b2_yom,
        b0_ylm, b1_ylm, b2_ylm,
        w_s_yvm, b0_yrm, out);
}